// round 13
// baseline (speedup 1.0000x reference)
#include <cuda_runtime.h>
#include <cuda_fp16.h>
#include <cstdint>
#include <cstddef>

#define BB 64
#define SEQ 512
#define EE 256
#define DDIM 512
#define NTAPS 16
#define DE (DDIM * EE)
#define THREADS 256

#define ROWB 80                       // 32 fp16 (64B) + 16B pad
#define AROWS 133
#define ABUF (AROWS * ROWB)           // 10640 per ec buffer
#define BSTAGE (128 * ROWB)           // 10240
#define SMEM_GEMM (2 * ABUF + 4 * BSTAGE)   // 62240

__device__ __align__(16) __half g_Wh[NTAPS * DE];     // fp16 combined taps
__device__ __align__(16) __half g_Xh[BB * SEQ * EE];  // fp16 features
__device__ float g_biasv[4 * DDIM];   // 0=interior 1=i0 2=i1 3=tail

// ---------------- helpers ----------------
__device__ __forceinline__ uint32_t smem_u32(const void* p) {
    uint32_t a;
    asm("{ .reg .u64 t; cvta.to.shared.u64 t, %1; cvt.u32.u64 %0, t; }" : "=r"(a) : "l"(p));
    return a;
}
__device__ __forceinline__ void cp16(uint32_t dst, const void* src) {
    asm volatile("cp.async.cg.shared.global [%0], [%1], 16;"
                 :: "r"(dst), "l"(src) : "memory");
}
#define CP_COMMIT() asm volatile("cp.async.commit_group;" ::: "memory")

#define LDSM4(r0, r1, r2, r3, ad) \
    asm volatile("ldmatrix.sync.aligned.m8n8.x4.shared.b16 {%0,%1,%2,%3}, [%4];" \
                 : "=r"(r0), "=r"(r1), "=r"(r2), "=r"(r3) : "r"(ad))

#define MMA_F16(d, a, bq) \
    asm volatile("mma.sync.aligned.m16n8k16.row.col.f32.f16.f16.f32 " \
                 "{%0,%1,%2,%3}, {%4,%5,%6,%7}, {%8,%9}, {%0,%1,%2,%3};" \
                 : "+f"((d)[0]), "+f"((d)[1]), "+f"((d)[2]), "+f"((d)[3]) \
                 : "r"((a)[0]), "r"((a)[1]), "r"((a)[2]), "r"((a)[3]), \
                   "r"((bq)[0]), "r"((bq)[1]))

// ---------------- preprocessing ----------------
__global__ void preproc_kernel(
    const float* __restrict__ W1, const float* __restrict__ b1,
    const float* __restrict__ W2, const float* __restrict__ b2,
    const float* __restrict__ W3, const float* __restrict__ b3,
    const float* __restrict__ W4, const float* __restrict__ b4)
{
    int idx = blockIdx.x * blockDim.x + threadIdx.x;
    if (idx >= DE) return;
    int d = idx >> 8, e = idx & 255;
    float w1 = W1[idx];
    const float* p2 = W2 + (size_t)idx * 2;
    float w20 = p2[0], w21 = p2[1];
    const float* p3 = W3 + (size_t)idx * 3;
    float w30 = p3[0], w31 = p3[1], w32 = p3[2];
    const float* p4 = W4 + (size_t)idx * 4;
    float w40 = p4[0], w41 = p4[1], w42 = p4[2], w43 = p4[3];

    float tap[NTAPS];
    tap[0] = w40;                                         // interior, delta=-2
    tap[1] = w30 + w40 + w41;
    tap[2] = w1 + w20 + w30 + w31 + w40 + w41 + w42;
    tap[3] = w21 + w31 + w32 + w41 + w42 + w43;
    tap[4] = w32 + w42 + w43;
    tap[5] = w43;
    tap[6] = w1;                                          // tail (unigram)
    tap[7]  = w1 + w20 + w30 + w40;                       // i==0 taps x0..x3
    tap[8]  = w21 + w31 + w41;
    tap[9]  = w32 + w42;
    tap[10] = w43;
    tap[11] = w30 + w40;                                  // i==1 taps x0..x4
    tap[12] = w1 + w20 + w30 + w31 + w40 + w41;
    tap[13] = w21 + w31 + w32 + w41 + w42;
    tap[14] = w32 + w42 + w43;
    tap[15] = w43;
#pragma unroll
    for (int t = 0; t < NTAPS; ++t)
        g_Wh[(size_t)t * DE + idx] = __float2half(tap[t]);
    if (e == 0) {
        float B1 = b1[d], B2 = b2[d], B3 = b3[d], B4 = b4[d];
        g_biasv[0 * DDIM + d] = B1 + B2 + 2.f * B3 + 3.f * B4;
        g_biasv[1 * DDIM + d] = B1 + B2 + B3 + B4;
        g_biasv[2 * DDIM + d] = B1 + B2 + 2.f * B3 + 2.f * B4;
        g_biasv[3 * DDIM + d] = B1;
    }
}

// x -> fp16
__global__ void convx_kernel(const float* __restrict__ x)
{
    int i = blockIdx.x * blockDim.x + threadIdx.x;
    const int N4 = BB * SEQ * EE / 4;
    if (i >= N4) return;
    float4 v = reinterpret_cast<const float4*>(x)[i];
    __half2* H = reinterpret_cast<__half2*>(g_Xh);
    H[2 * i + 0] = __floats2half2_rn(v.x, v.y);
    H[2 * i + 1] = __floats2half2_rn(v.z, v.w);
}

// ---------------- fp16 single-pass HMMA GEMM, M=128 tiles, 2 CTA/SM ----------------
// grid = 1032: [0,512) interior, [512,1024) tail, [1024,1032) boundary
// 256 threads = 8 warps (4 wm x 2 wn), warp tile 32x64.
__global__ void __launch_bounds__(THREADS, 2) gemm_kernel(float* __restrict__ out)
{
    extern __shared__ char smem[];
    const uint32_t sb = smem_u32(smem);
    const int tid = threadIdx.x;
    const int lane = tid & 31;
    const int warp = tid >> 5;
    const int wm = warp >> 1;          // 0..3
    const int wn = warp & 1;           // 0..1

    const int id = blockIdx.x;
    bool bdry = false;
    int T, tap0, bidx, b = 0, cls = 0, dn, my = 0, abase = 0, obase = 0;
    if (id < 512) {
        b = id >> 3; my = (id >> 2) & 1; dn = id & 3;
        T = 6; tap0 = 0; bidx = 0;
        abase = b * SEQ + my * 128; obase = abase + 2;
    } else if (id < 1024) {
        int q = id - 512; b = q >> 3; my = (q >> 2) & 1; dn = q & 3;
        T = 1; tap0 = 6; bidx = 3;
        abase = b * SEQ + 256 + my * 128; obase = abase;
    } else {
        int q = id - 1024; cls = q >> 2; dn = q & 3; bdry = true;
        T = 4 + cls; tap0 = 7 + 4 * cls; bidx = 1 + cls;
    }
    const int d0 = dn * 128;
    const int C = 8 * T;
    const int arows = (T == 1) ? 128 : 133;   // interior needs M+5
    const bool active = !bdry || (wm < 2);
    const bool late = (T < 3);

    // ---- loaders ----
    auto loadA = [&](int ec) {                 // hoisted A (interior/tail)
        const uint32_t Ab = sb + (uint32_t)((ec & 1) * ABUF);
        const int ecol = ec * 32;
        const int nops = arows * 4;
        for (int q = tid; q < nops; q += THREADS) {
            int row = q >> 2, seg = q & 3;
            cp16(Ab + (uint32_t)(row * ROWB + seg * 16),
                 g_Xh + (long)(abase + row) * EE + ecol + seg * 8);
        }
    };
    auto loadA_bdry = [&](int k) {             // per-chunk A, 4-slot ring
        const int ec = k / T, t = k - ec * T;
        const int slot = k & 3;
        const uint32_t Ab = sb + (uint32_t)((slot >> 1) * ABUF + (slot & 1) * (64 * ROWB));
        const int ecol = ec * 32;
        {
            int row = tid >> 2, seg = tid & 3;    // 64 rows x 4 segs = 256 ops
            cp16(Ab + (uint32_t)(row * ROWB + seg * 16),
                 g_Xh + ((long)row * SEQ + t) * EE + ecol + seg * 8);
        }
    };
    auto loadB = [&](int k) {
        const int ec = k / T, t = k - ec * T;
        const uint32_t Bs = sb + 2 * ABUF + (uint32_t)((k & 3) * BSTAGE);
        const __half* wb = g_Wh + (size_t)(tap0 + t) * DE + (size_t)d0 * EE + ec * 32;
#pragma unroll
        for (int j = 0; j < 2; ++j) {
            int q = tid + THREADS * j;
            int row = q >> 2, seg = q & 3;
            cp16(Bs + (uint32_t)(row * ROWB + seg * 16),
                 wb + (size_t)row * EE + seg * 8);
        }
    };
    auto issue = [&](int k) {
        if (bdry) loadA_bdry(k);
        else if (k % T == 0) loadA(k / T);
        loadB(k);
        CP_COMMIT();
    };

    float acc[2][8][4];
#pragma unroll
    for (int mi = 0; mi < 2; ++mi)
#pragma unroll
        for (int nb = 0; nb < 8; ++nb)
#pragma unroll
            for (int q = 0; q < 4; ++q) acc[mi][nb][q] = 0.f;

    int committed = 0;
    const int depth = late ? 2 : 3;
    for (int k = 0; k < depth; ++k) { issue(k); ++committed; }

    for (int k = 0; k < C; ++k) {
        const int n = committed - (k + 1);
        if (n == 0) asm volatile("cp.async.wait_group 0;" ::: "memory");
        else if (n == 1) asm volatile("cp.async.wait_group 1;" ::: "memory");
        else asm volatile("cp.async.wait_group 2;" ::: "memory");
        __syncthreads();
        if (!late && k + 3 < C) { issue(k + 3); ++committed; }

        const int ec = k / T, t = k - ec * T;
        const int slot = k & 3;
        const uint32_t Ab = bdry
            ? sb + (uint32_t)((slot >> 1) * ABUF + (slot & 1) * (64 * ROWB))
            : sb + (uint32_t)((ec & 1) * ABUF) + (uint32_t)(t * ROWB);
        const uint32_t Bs = sb + 2 * ABUF + (uint32_t)((k & 3) * BSTAGE);

        if (active) {
#pragma unroll
            for (int ks = 0; ks < 2; ++ks) {
                uint32_t a[2][4];
#pragma unroll
                for (int mi = 0; mi < 2; ++mi) {
                    int rrow = 32 * wm + 16 * mi + (lane & 7) + ((lane >> 3) & 1) * 8;
                    uint32_t ad = Ab + (uint32_t)(rrow * ROWB) + ks * 32 + ((lane >> 4) << 4);
                    LDSM4(a[mi][0], a[mi][1], a[mi][2], a[mi][3], ad);
                }
                uint32_t bq[8][2];
#pragma unroll
                for (int nb2 = 0; nb2 < 4; ++nb2) {
                    int nrow = 64 * wn + 16 * nb2 + (lane & 7) + ((lane >> 4) << 3);
                    uint32_t ad = Bs + (uint32_t)(nrow * ROWB) + ks * 32 + (((lane >> 3) & 1) << 4);
                    uint32_t r0, r1, r2, r3;
                    LDSM4(r0, r1, r2, r3, ad);
                    bq[2 * nb2][0] = r0;     bq[2 * nb2][1] = r1;
                    bq[2 * nb2 + 1][0] = r2; bq[2 * nb2 + 1][1] = r3;
                }
#pragma unroll
                for (int mi = 0; mi < 2; ++mi)
#pragma unroll
                    for (int nb = 0; nb < 8; ++nb)
                        MMA_F16(acc[mi][nb], a[mi], bq[nb]);
            }
        }
        if (late && k + 2 < C) {
            __syncthreads();
            issue(k + 2); ++committed;
        }
    }

    // ---- epilogue ----
    if (active) {
        const int mlim = bdry ? 64 : ((T == 6 && my == 1) ? 126 : 128);
#pragma unroll
        for (int mi = 0; mi < 2; ++mi) {
#pragma unroll
            for (int nb = 0; nb < 8; ++nb) {
                int m0 = 32 * wm + 16 * mi + (lane >> 2);
                int n0 = 64 * wn + 8 * nb + (lane & 3) * 2;
                float2 bv = *reinterpret_cast<const float2*>(&g_biasv[bidx * DDIM + d0 + n0]);
#pragma unroll
                for (int h = 0; h < 2; ++h) {
                    int m = m0 + 8 * h;
                    if (m < mlim) {
                        long orow = bdry ? ((long)m * SEQ + cls) : (long)(obase + m);
                        float2 v;
                        v.x = acc[mi][nb][2 * h + 0] + bv.x;
                        v.y = acc[mi][nb][2 * h + 1] + bv.y;
                        *reinterpret_cast<float2*>(&out[orow * DDIM + d0 + n0]) = v;
                    }
                }
            }
        }
    }
}

// ---------------- host ----------------
extern "C" void kernel_launch(void* const* d_in, const int* in_sizes, int n_in,
                              void* d_out, int out_size)
{
    (void)in_sizes; (void)n_in; (void)out_size;
    const float* x  = (const float*)d_in[0];
    const float* W1 = (const float*)d_in[1];
    const float* b1 = (const float*)d_in[2];
    const float* W2 = (const float*)d_in[3];
    const float* b2 = (const float*)d_in[4];
    const float* W3 = (const float*)d_in[5];
    const float* b3 = (const float*)d_in[6];
    const float* W4 = (const float*)d_in[7];
    const float* b4 = (const float*)d_in[8];
    float* out = (float*)d_out;

    preproc_kernel<<<(DE + 255) / 256, 256>>>(W1, b1, W2, b2, W3, b3, W4, b4);
    convx_kernel<<<(BB * SEQ * EE / 4 + 255) / 256, 256>>>(x);

    cudaFuncSetAttribute(gemm_kernel,
                         cudaFuncAttributeMaxDynamicSharedMemorySize, SMEM_GEMM);
    gemm_kernel<<<1032, THREADS, SMEM_GEMM>>>(out);
}

// round 16
// speedup vs baseline: 1.7199x; 1.7199x over previous
#include <cuda_runtime.h>
#include <cuda_fp16.h>
#include <cstdint>
#include <cstddef>

#define BB 64
#define SEQ 512
#define EE 256
#define DDIM 512
#define NTAPS 16
#define DE (DDIM * EE)
#define THREADS 512

#define ROWB 144                      // 64 fp16 (128B) + 16B pad
#define AROWS 320
#define ABUF (AROWS * ROWB)           // 46080 per ec buffer
#define BSTAGE (128 * ROWB)           // 18432
#define SMEM_GEMM (2 * ABUF + 4 * BSTAGE)   // 165888

__device__ __align__(16) __half g_Wh[NTAPS * DE];     // fp16 combined taps
__device__ __align__(16) __half g_Xh[BB * SEQ * EE];  // fp16 features
__device__ float g_biasv[4 * DDIM];   // 0=interior 1=i0 2=i1 3=tail

// ---------------- helpers ----------------
__device__ __forceinline__ uint32_t smem_u32(const void* p) {
    uint32_t a;
    asm("{ .reg .u64 t; cvta.to.shared.u64 t, %1; cvt.u32.u64 %0, t; }" : "=r"(a) : "l"(p));
    return a;
}
__device__ __forceinline__ void cp16(uint32_t dst, const void* src) {
    asm volatile("cp.async.cg.shared.global [%0], [%1], 16;"
                 :: "r"(dst), "l"(src) : "memory");
}
#define CP_COMMIT() asm volatile("cp.async.commit_group;" ::: "memory")

#define LDSM4(r0, r1, r2, r3, ad) \
    asm volatile("ldmatrix.sync.aligned.m8n8.x4.shared.b16 {%0,%1,%2,%3}, [%4];" \
                 : "=r"(r0), "=r"(r1), "=r"(r2), "=r"(r3) : "r"(ad))

#define MMA_F16(d, a, bq) \
    asm volatile("mma.sync.aligned.m16n8k16.row.col.f32.f16.f16.f32 " \
                 "{%0,%1,%2,%3}, {%4,%5,%6,%7}, {%8,%9}, {%0,%1,%2,%3};" \
                 : "+f"((d)[0]), "+f"((d)[1]), "+f"((d)[2]), "+f"((d)[3]) \
                 : "r"((a)[0]), "r"((a)[1]), "r"((a)[2]), "r"((a)[3]), \
                   "r"((bq)[0]), "r"((bq)[1]))

// ---------------- preprocessing ----------------
__global__ void preproc_kernel(
    const float* __restrict__ W1, const float* __restrict__ b1,
    const float* __restrict__ W2, const float* __restrict__ b2,
    const float* __restrict__ W3, const float* __restrict__ b3,
    const float* __restrict__ W4, const float* __restrict__ b4)
{
    int idx = blockIdx.x * blockDim.x + threadIdx.x;
    if (idx >= DE) return;
    int d = idx >> 8, e = idx & 255;
    float w1 = W1[idx];
    const float* p2 = W2 + (size_t)idx * 2;
    float w20 = p2[0], w21 = p2[1];
    const float* p3 = W3 + (size_t)idx * 3;
    float w30 = p3[0], w31 = p3[1], w32 = p3[2];
    const float* p4 = W4 + (size_t)idx * 4;
    float w40 = p4[0], w41 = p4[1], w42 = p4[2], w43 = p4[3];

    float tap[NTAPS];
    tap[0] = w40;                                         // interior, delta=-2
    tap[1] = w30 + w40 + w41;
    tap[2] = w1 + w20 + w30 + w31 + w40 + w41 + w42;
    tap[3] = w21 + w31 + w32 + w41 + w42 + w43;
    tap[4] = w32 + w42 + w43;
    tap[5] = w43;
    tap[6] = w1;                                          // tail (unigram)
    tap[7]  = w1 + w20 + w30 + w40;                       // i==0 taps x0..x3
    tap[8]  = w21 + w31 + w41;
    tap[9]  = w32 + w42;
    tap[10] = w43;
    tap[11] = w30 + w40;                                  // i==1 taps x0..x4
    tap[12] = w1 + w20 + w30 + w31 + w40 + w41;
    tap[13] = w21 + w31 + w32 + w41 + w42;
    tap[14] = w32 + w42 + w43;
    tap[15] = w43;
#pragma unroll
    for (int t = 0; t < NTAPS; ++t)
        g_Wh[(size_t)t * DE + idx] = __float2half(tap[t]);
    if (e == 0) {
        float B1 = b1[d], B2 = b2[d], B3 = b3[d], B4 = b4[d];
        g_biasv[0 * DDIM + d] = B1 + B2 + 2.f * B3 + 3.f * B4;
        g_biasv[1 * DDIM + d] = B1 + B2 + B3 + B4;
        g_biasv[2 * DDIM + d] = B1 + B2 + 2.f * B3 + 2.f * B4;
        g_biasv[3 * DDIM + d] = B1;
    }
}

// x -> fp16
__global__ void convx_kernel(const float* __restrict__ x)
{
    int i = blockIdx.x * blockDim.x + threadIdx.x;
    const int N4 = BB * SEQ * EE / 4;
    if (i >= N4) return;
    float4 v = reinterpret_cast<const float4*>(x)[i];
    __half2* H = reinterpret_cast<__half2*>(g_Xh);
    H[2 * i + 0] = __floats2half2_rn(v.x, v.y);
    H[2 * i + 1] = __floats2half2_rn(v.z, v.w);
}

// ---------------- fp16 single-pass HMMA GEMM, hoisted-A, K=64 chunks ----------------
// grid = 520 (LPT order): [0,8) boundary, [8,264) interior, [264,520) tail
// 512 threads = 16 warps (8 wm x 2 wn), warp tile 32x64.
__global__ void __launch_bounds__(THREADS, 1) gemm_kernel(float* __restrict__ out)
{
    extern __shared__ char smem[];
    const uint32_t sb = smem_u32(smem);
    const int tid = threadIdx.x;
    const int lane = tid & 31;
    const int warp = tid >> 5;
    const int wm = warp >> 1;          // 0..7
    const int wn = warp & 1;           // 0..1

    const int id = blockIdx.x;
    bool bdry = false;
    int T, tap0, bidx, cls = 0, dn, abase = 0, obase = 0;
    if (id < 8) {
        cls = id >> 2; dn = id & 3; bdry = true;
        T = 4 + cls; tap0 = 7 + 4 * cls; bidx = 1 + cls;
    } else if (id < 264) {
        int q = id - 8; int b = q >> 2; dn = q & 3;
        T = 6; tap0 = 0; bidx = 0; abase = b * SEQ; obase = abase + 2;
    } else {
        int q = id - 264; int b = q >> 2; dn = q & 3;
        T = 1; tap0 = 6; bidx = 3; abase = b * SEQ + 256; obase = abase;
    }
    const int d0 = dn * 128;
    const int C = 4 * T;               // chunks of K=64
    const int arows = bdry ? T * 64 : (T == 1 ? 256 : 261);
    const bool active = !bdry || (wm < 2);
    const bool late = (T < 3);

    // ---- loaders ----
    auto loadA = [&](int ec) {
        const uint32_t Ab = sb + (uint32_t)((ec & 1) * ABUF);
        const int ecol = ec * 64;
        const int nops = arows * 8;    // 8 x 16B per 128B row
        for (int q = tid; q < nops; q += THREADS) {
            int row = q >> 3, seg = q & 7;
            long gr = bdry ? ((long)(row & 63) * SEQ + (row >> 6))
                           : (long)(abase + row);
            cp16(Ab + (uint32_t)(row * ROWB + seg * 16),
                 g_Xh + gr * EE + ecol + seg * 8);
        }
    };
    auto loadB = [&](int k) {
        const int ec = k / T, t = k - ec * T;
        const uint32_t Bs = sb + 2 * ABUF + (uint32_t)((k & 3) * BSTAGE);
        const __half* wb = g_Wh + (size_t)(tap0 + t) * DE + (size_t)d0 * EE + ec * 64;
#pragma unroll
        for (int j = 0; j < 2; ++j) {
            int q = tid + THREADS * j;
            int row = q >> 3, seg = q & 7;
            cp16(Bs + (uint32_t)(row * ROWB + seg * 16),
                 wb + (size_t)row * EE + seg * 8);
        }
    };
    auto issue = [&](int k) {
        if (k % T == 0) loadA(k / T);
        loadB(k);
        CP_COMMIT();
    };

    float acc[2][8][4];
#pragma unroll
    for (int mi = 0; mi < 2; ++mi)
#pragma unroll
        for (int nb = 0; nb < 8; ++nb)
#pragma unroll
            for (int q = 0; q < 4; ++q) acc[mi][nb][q] = 0.f;

    int committed = 0;
    const int depth = late ? 2 : 3;
    for (int k = 0; k < depth && k < C; ++k) { issue(k); ++committed; }

    for (int k = 0; k < C; ++k) {
        const int n = committed - (k + 1);
        if (n == 0) asm volatile("cp.async.wait_group 0;" ::: "memory");
        else if (n == 1) asm volatile("cp.async.wait_group 1;" ::: "memory");
        else asm volatile("cp.async.wait_group 2;" ::: "memory");
        __syncthreads();
        if (!late && k + 3 < C) { issue(k + 3); ++committed; }

        const int ec = k / T, t = k - ec * T;
        const uint32_t Ab = sb + (uint32_t)((ec & 1) * ABUF)
                               + (uint32_t)((bdry ? t * 64 : t) * ROWB);
        const uint32_t Bs = sb + 2 * ABUF + (uint32_t)((k & 3) * BSTAGE);

        if (active) {
#pragma unroll
            for (int ks = 0; ks < 4; ++ks) {
                uint32_t a[2][4];
#pragma unroll
                for (int mi = 0; mi < 2; ++mi) {
                    int rrow = 32 * wm + 16 * mi + (lane & 7) + ((lane >> 3) & 1) * 8;
                    uint32_t ad = Ab + (uint32_t)(rrow * ROWB) + ks * 32 + ((lane >> 4) << 4);
                    LDSM4(a[mi][0], a[mi][1], a[mi][2], a[mi][3], ad);
                }
                uint32_t bq[8][2];
#pragma unroll
                for (int nb2 = 0; nb2 < 4; ++nb2) {
                    int nrow = 64 * wn + 16 * nb2 + (lane & 7) + ((lane >> 4) << 3);
                    uint32_t ad = Bs + (uint32_t)(nrow * ROWB) + ks * 32 + (((lane >> 3) & 1) << 4);
                    uint32_t r0, r1, r2, r3;
                    LDSM4(r0, r1, r2, r3, ad);
                    bq[2 * nb2][0] = r0;     bq[2 * nb2][1] = r1;
                    bq[2 * nb2 + 1][0] = r2; bq[2 * nb2 + 1][1] = r3;
                }
#pragma unroll
                for (int mi = 0; mi < 2; ++mi)
#pragma unroll
                    for (int nb = 0; nb < 8; ++nb)
                        MMA_F16(acc[mi][nb], a[mi], bq[nb]);
            }
        }
        if (late && k + 2 < C) {
            __syncthreads();
            issue(k + 2); ++committed;
        }
    }

    // ---- epilogue ----
    if (active) {
        const int mlim = bdry ? 64 : (T == 6 ? 254 : 256);
#pragma unroll
        for (int mi = 0; mi < 2; ++mi) {
#pragma unroll
            for (int nb = 0; nb < 8; ++nb) {
                int m0 = 32 * wm + 16 * mi + (lane >> 2);
                int n0 = 64 * wn + 8 * nb + (lane & 3) * 2;
                float2 bv = *reinterpret_cast<const float2*>(&g_biasv[bidx * DDIM + d0 + n0]);
#pragma unroll
                for (int h = 0; h < 2; ++h) {
                    int m = m0 + 8 * h;
                    if (m < mlim) {
                        long orow = bdry ? ((long)m * SEQ + cls) : (long)(obase + m);
                        float2 v;
                        v.x = acc[mi][nb][2 * h + 0] + bv.x;
                        v.y = acc[mi][nb][2 * h + 1] + bv.y;
                        *reinterpret_cast<float2*>(&out[orow * DDIM + d0 + n0]) = v;
                    }
                }
            }
        }
    }
}

// ---------------- host ----------------
extern "C" void kernel_launch(void* const* d_in, const int* in_sizes, int n_in,
                              void* d_out, int out_size)
{
    (void)in_sizes; (void)n_in; (void)out_size;
    const float* x  = (const float*)d_in[0];
    const float* W1 = (const float*)d_in[1];
    const float* b1 = (const float*)d_in[2];
    const float* W2 = (const float*)d_in[3];
    const float* b2 = (const float*)d_in[4];
    const float* W3 = (const float*)d_in[5];
    const float* b3 = (const float*)d_in[6];
    const float* W4 = (const float*)d_in[7];
    const float* b4 = (const float*)d_in[8];
    float* out = (float*)d_out;

    preproc_kernel<<<(DE + 255) / 256, 256>>>(W1, b1, W2, b2, W3, b3, W4, b4);
    convx_kernel<<<(BB * SEQ * EE / 4 + 255) / 256, 256>>>(x);

    cudaFuncSetAttribute(gemm_kernel,
                         cudaFuncAttributeMaxDynamicSharedMemorySize, SMEM_GEMM);
    gemm_kernel<<<520, THREADS, SMEM_GEMM>>>(out);
}

// round 17
// speedup vs baseline: 1.9938x; 1.1592x over previous
#include <cuda_runtime.h>
#include <cuda_fp16.h>
#include <cstdint>
#include <cstddef>

#define BB 64
#define SEQ 512
#define EE 256
#define DDIM 512
#define NTAPS 16
#define DE (DDIM * EE)
#define THREADS 512

#define ROWB 144                      // 64 fp16 (128B) + 16B pad
#define AROWS 320
#define ABUF (AROWS * ROWB)           // 46080 per ec buffer
#define BSTAGE (128 * ROWB)           // 18432
#define NBST 6
#define SMEM_GEMM (2 * ABUF + NBST * BSTAGE)   // 202752

__device__ __align__(16) __half g_Wh[NTAPS * DE];     // fp16 combined taps
__device__ __align__(16) __half g_Xh[BB * SEQ * EE];  // fp16 features
__device__ float g_biasv[4 * DDIM];   // 0=interior 1=i0 2=i1 3=tail

// ---------------- helpers ----------------
__device__ __forceinline__ uint32_t smem_u32(const void* p) {
    uint32_t a;
    asm("{ .reg .u64 t; cvta.to.shared.u64 t, %1; cvt.u32.u64 %0, t; }" : "=r"(a) : "l"(p));
    return a;
}
__device__ __forceinline__ void cp16(uint32_t dst, const void* src) {
    asm volatile("cp.async.cg.shared.global [%0], [%1], 16;"
                 :: "r"(dst), "l"(src) : "memory");
}
#define CP_COMMIT() asm volatile("cp.async.commit_group;" ::: "memory")

#define LDSM4(r0, r1, r2, r3, ad) \
    asm volatile("ldmatrix.sync.aligned.m8n8.x4.shared.b16 {%0,%1,%2,%3}, [%4];" \
                 : "=r"(r0), "=r"(r1), "=r"(r2), "=r"(r3) : "r"(ad))

#define MMA_F16(d, a, bq) \
    asm volatile("mma.sync.aligned.m16n8k16.row.col.f32.f16.f16.f32 " \
                 "{%0,%1,%2,%3}, {%4,%5,%6,%7}, {%8,%9}, {%0,%1,%2,%3};" \
                 : "+f"((d)[0]), "+f"((d)[1]), "+f"((d)[2]), "+f"((d)[3]) \
                 : "r"((a)[0]), "r"((a)[1]), "r"((a)[2]), "r"((a)[3]), \
                   "r"((bq)[0]), "r"((bq)[1]))

// ---------------- fused preprocessing: taps->fp16 + x->fp16 ----------------
__global__ void prep_kernel(
    const float* __restrict__ x,
    const float* __restrict__ W1, const float* __restrict__ b1,
    const float* __restrict__ W2, const float* __restrict__ b2,
    const float* __restrict__ W3, const float* __restrict__ b3,
    const float* __restrict__ W4, const float* __restrict__ b4)
{
    if (blockIdx.x < 512) {
        int idx = blockIdx.x * blockDim.x + threadIdx.x;
        int d = idx >> 8, e = idx & 255;
        float w1 = W1[idx];
        const float* p2 = W2 + (size_t)idx * 2;
        float w20 = p2[0], w21 = p2[1];
        const float* p3 = W3 + (size_t)idx * 3;
        float w30 = p3[0], w31 = p3[1], w32 = p3[2];
        const float* p4 = W4 + (size_t)idx * 4;
        float w40 = p4[0], w41 = p4[1], w42 = p4[2], w43 = p4[3];

        float tap[NTAPS];
        tap[0] = w40;                                         // interior, delta=-2
        tap[1] = w30 + w40 + w41;
        tap[2] = w1 + w20 + w30 + w31 + w40 + w41 + w42;
        tap[3] = w21 + w31 + w32 + w41 + w42 + w43;
        tap[4] = w32 + w42 + w43;
        tap[5] = w43;
        tap[6] = w1;                                          // tail (unigram)
        tap[7]  = w1 + w20 + w30 + w40;                       // i==0 taps x0..x3
        tap[8]  = w21 + w31 + w41;
        tap[9]  = w32 + w42;
        tap[10] = w43;
        tap[11] = w30 + w40;                                  // i==1 taps x0..x4
        tap[12] = w1 + w20 + w30 + w31 + w40 + w41;
        tap[13] = w21 + w31 + w32 + w41 + w42;
        tap[14] = w32 + w42 + w43;
        tap[15] = w43;
#pragma unroll
        for (int t = 0; t < NTAPS; ++t)
            g_Wh[(size_t)t * DE + idx] = __float2half(tap[t]);
        if (e == 0) {
            float B1 = b1[d], B2 = b2[d], B3 = b3[d], B4 = b4[d];
            g_biasv[0 * DDIM + d] = B1 + B2 + 2.f * B3 + 3.f * B4;
            g_biasv[1 * DDIM + d] = B1 + B2 + B3 + B4;
            g_biasv[2 * DDIM + d] = B1 + B2 + 2.f * B3 + 2.f * B4;
            g_biasv[3 * DDIM + d] = B1;
        }
    } else {
        int i = (blockIdx.x - 512) * blockDim.x + threadIdx.x;
        float4 v = reinterpret_cast<const float4*>(x)[i];
        __half2* H = reinterpret_cast<__half2*>(g_Xh);
        H[2 * i + 0] = __floats2half2_rn(v.x, v.y);
        H[2 * i + 1] = __floats2half2_rn(v.z, v.w);
    }
}

// ---------------- fp16 HMMA GEMM, hoisted-A, K=64 chunks, paired interior ----------------
// grid = 520 (LPT order): [0,8) boundary, [8,264) interior, [264,520) tail
// 512 threads = 16 warps (8 wm x 2 wn), warp tile 32x64.
__global__ void __launch_bounds__(THREADS, 1) gemm_kernel(float* __restrict__ out)
{
    extern __shared__ char smem[];
    const uint32_t sb = smem_u32(smem);
    const int tid = threadIdx.x;
    const int lane = tid & 31;
    const int warp = tid >> 5;
    const int wm = warp >> 1;          // 0..7
    const int wn = warp & 1;           // 0..1

    const int id = blockIdx.x;
    bool bdry = false;
    int T, tap0, bidx, cls = 0, dn, abase = 0, obase = 0;
    if (id < 8) {
        cls = id >> 2; dn = id & 3; bdry = true;
        T = 4 + cls; tap0 = 7 + 4 * cls; bidx = 1 + cls;
    } else if (id < 264) {
        int q = id - 8; int b = q >> 2; dn = q & 3;
        T = 6; tap0 = 0; bidx = 0; abase = b * SEQ; obase = abase + 2;
    } else {
        int q = id - 264; int b = q >> 2; dn = q & 3;
        T = 1; tap0 = 6; bidx = 3; abase = b * SEQ + 256; obase = abase;
    }
    const int d0 = dn * 128;
    const int C = 4 * T;               // chunks of K=64
    const int arows = bdry ? T * 64 : (T == 1 ? 256 : 261);
    const bool active = !bdry || (wm < 2);

    // ---- loaders ----
    auto loadA = [&](int ec) {
        const uint32_t Ab = sb + (uint32_t)((ec & 1) * ABUF);
        const int ecol = ec * 64;
        const int nops = arows * 8;    // 8 x 16B per 128B row
        for (int q = tid; q < nops; q += THREADS) {
            int row = q >> 3, seg = q & 7;
            long gr = bdry ? ((long)(row & 63) * SEQ + (row >> 6))
                           : (long)(abase + row);
            cp16(Ab + (uint32_t)(row * ROWB + seg * 16),
                 g_Xh + gr * EE + ecol + seg * 8);
        }
    };
    auto loadB = [&](int k) {
        const int ec = k / T, t = k - ec * T;
        const uint32_t Bs = sb + 2 * ABUF + (uint32_t)((k % NBST) * BSTAGE);
        const __half* wb = g_Wh + (size_t)(tap0 + t) * DE + (size_t)d0 * EE + ec * 64;
#pragma unroll
        for (int j = 0; j < 2; ++j) {
            int q = tid + THREADS * j;
            int row = q >> 3, seg = q & 7;
            cp16(Bs + (uint32_t)(row * ROWB + seg * 16),
                 wb + (size_t)row * EE + seg * 8);
        }
    };
    auto issue = [&](int k) {
        if (k % T == 0) loadA(k / T);
        loadB(k);
        CP_COMMIT();
    };

    float acc[2][8][4];
#pragma unroll
    for (int mi = 0; mi < 2; ++mi)
#pragma unroll
        for (int nb = 0; nb < 8; ++nb)
#pragma unroll
            for (int q = 0; q < 4; ++q) acc[mi][nb][q] = 0.f;

    // ---- compute one K=64 chunk ----
    auto compute = [&](int k) {
        const int ec = k / T, t = k - ec * T;
        const uint32_t Ab = sb + (uint32_t)((ec & 1) * ABUF)
                               + (uint32_t)((bdry ? t * 64 : t) * ROWB);
        const uint32_t Bs = sb + 2 * ABUF + (uint32_t)((k % NBST) * BSTAGE);
#pragma unroll
        for (int ks = 0; ks < 4; ++ks) {
            uint32_t a[2][4];
#pragma unroll
            for (int mi = 0; mi < 2; ++mi) {
                int rrow = 32 * wm + 16 * mi + (lane & 7) + ((lane >> 3) & 1) * 8;
                uint32_t ad = Ab + (uint32_t)(rrow * ROWB) + ks * 32 + ((lane >> 4) << 4);
                LDSM4(a[mi][0], a[mi][1], a[mi][2], a[mi][3], ad);
            }
            uint32_t bq[8][2];
#pragma unroll
            for (int nb2 = 0; nb2 < 4; ++nb2) {
                int nrow = 64 * wn + 16 * nb2 + (lane & 7) + ((lane >> 4) << 3);
                uint32_t ad = Bs + (uint32_t)(nrow * ROWB) + ks * 32 + (((lane >> 3) & 1) << 4);
                uint32_t r0, r1, r2, r3;
                LDSM4(r0, r1, r2, r3, ad);
                bq[2 * nb2][0] = r0;     bq[2 * nb2][1] = r1;
                bq[2 * nb2 + 1][0] = r2; bq[2 * nb2 + 1][1] = r3;
            }
#pragma unroll
            for (int mi = 0; mi < 2; ++mi)
#pragma unroll
                for (int nb = 0; nb < 8; ++nb)
                    MMA_F16(acc[mi][nb], a[mi], bq[nb]);
        }
    };

    if (T == 6) {
        // ---- paired-chunk interior loop: one wait+sync per 2 chunks ----
        const int P = C / 2;           // 12 pairs
        issue(0); issue(1); issue(2); issue(3);   // pairs 0,1
        for (int j = 0; j < P; ++j) {
            if (j == P - 1) asm volatile("cp.async.wait_group 0;" ::: "memory");
            else            asm volatile("cp.async.wait_group 2;" ::: "memory");
            __syncthreads();
            if (2 * j + 4 < C) { issue(2 * j + 4); issue(2 * j + 5); }
            compute(2 * j);
            compute(2 * j + 1);
        }
    } else {
        // ---- generic loop (tail T=1, boundary T=4,5) ----
        const bool late = (T < 3);
        int committed = 0;
        const int depth = late ? 2 : 3;
        for (int k = 0; k < depth && k < C; ++k) { issue(k); ++committed; }
        for (int k = 0; k < C; ++k) {
            const int n = committed - (k + 1);
            if (n == 0) asm volatile("cp.async.wait_group 0;" ::: "memory");
            else if (n == 1) asm volatile("cp.async.wait_group 1;" ::: "memory");
            else asm volatile("cp.async.wait_group 2;" ::: "memory");
            __syncthreads();
            if (!late && k + 3 < C) { issue(k + 3); ++committed; }
            if (active) compute(k);
            if (late && k + 2 < C) {
                __syncthreads();
                issue(k + 2); ++committed;
            }
        }
    }

    // ---- epilogue ----
    if (active) {
        const int mlim = bdry ? 64 : (T == 6 ? 254 : 256);
#pragma unroll
        for (int mi = 0; mi < 2; ++mi) {
#pragma unroll
            for (int nb = 0; nb < 8; ++nb) {
                int m0 = 32 * wm + 16 * mi + (lane >> 2);
                int n0 = 64 * wn + 8 * nb + (lane & 3) * 2;
                float2 bv = *reinterpret_cast<const float2*>(&g_biasv[bidx * DDIM + d0 + n0]);
#pragma unroll
                for (int h = 0; h < 2; ++h) {
                    int m = m0 + 8 * h;
                    if (m < mlim) {
                        long orow = bdry ? ((long)m * SEQ + cls) : (long)(obase + m);
                        float2 v;
                        v.x = acc[mi][nb][2 * h + 0] + bv.x;
                        v.y = acc[mi][nb][2 * h + 1] + bv.y;
                        *reinterpret_cast<float2*>(&out[orow * DDIM + d0 + n0]) = v;
                    }
                }
            }
        }
    }
}

// ---------------- host ----------------
extern "C" void kernel_launch(void* const* d_in, const int* in_sizes, int n_in,
                              void* d_out, int out_size)
{
    (void)in_sizes; (void)n_in; (void)out_size;
    const float* x  = (const float*)d_in[0];
    const float* W1 = (const float*)d_in[1];
    const float* b1 = (const float*)d_in[2];
    const float* W2 = (const float*)d_in[3];
    const float* b2 = (const float*)d_in[4];
    const float* W3 = (const float*)d_in[5];
    const float* b3 = (const float*)d_in[6];
    const float* W4 = (const float*)d_in[7];
    const float* b4 = (const float*)d_in[8];
    float* out = (float*)d_out;

    // fused: blocks [0,512) build taps/bias, blocks [512,8704) convert x to fp16
    prep_kernel<<<512 + (BB * SEQ * EE / 4) / 256, 256>>>(
        x, W1, b1, W2, b2, W3, b3, W4, b4);

    cudaFuncSetAttribute(gemm_kernel,
                         cudaFuncAttributeMaxDynamicSharedMemorySize, SMEM_GEMM);
    gemm_kernel<<<520, THREADS, SMEM_GEMM>>>(out);
}